// round 2
// baseline (speedup 1.0000x reference)
#include <cuda_runtime.h>
#include <math.h>

#define NB   8
#define NN   256
#define NH   8
#define NLAT 32
#define SC   0.35355339059327373f

__device__ __align__(16) float g_Q   [NB*NN*64];
__device__ __align__(16) float g_Kt  [NB*64*NN];     // [b][hk][j] pre-scaled
__device__ __align__(16) float g_Vt  [NB*NH*NN*8];   // [b][h][j][d]
__device__ __align__(16) float g_S   [NB*NH*NN*NN];  // raw scores
__device__ unsigned int        g_M   [NB*NH];
__device__ __align__(16) float g_pattn[NB*NN*64];
__device__ __align__(16) float g_hc  [NB*NN*64];
__device__ __align__(16) float g_Kc  [NB*NN*64];
__device__ __align__(16) float g_Vc  [NB*NN*64];
__device__ __align__(16) float g_q   [NB*NLAT*64];
__device__ __align__(16) float g_q2  [NB*NLAT*64];
__device__ __align__(16) float g_Kl  [NB*NLAT*64];
__device__ __align__(16) float g_Vl  [NB*NLAT*64];

// -------- K0: Q, K*SCALE (transposed), V (head-major); also reset g_M --------
__global__ void k_qkv(const float* __restrict__ p, const float* __restrict__ wq,
                      const float* __restrict__ wk, const float* __restrict__ wv) {
    int bi = blockIdx.x, t = threadIdx.x;
    __shared__ float pr[64];
    pr[t] = p[bi*64 + t];
    if (bi == 0) g_M[t] = 0u;
    __syncthreads();
    float aq = 0.f, ak = 0.f, av = 0.f;
#pragma unroll 8
    for (int c = 0; c < 64; c++) {
        float pv = pr[c];
        aq = fmaf(pv, wq[c*64 + t], aq);
        ak = fmaf(pv, wk[c*64 + t], ak);
        av = fmaf(pv, wv[c*64 + t], av);
    }
    int b = bi >> 8, j = bi & 255;
    g_Q[bi*64 + t] = aq;
    g_Kt[(b*64 + t)*256 + j] = ak * SC;
    g_Vt[(((b*8 + (t >> 3))*256) + j)*8 + (t & 7)] = av;
}

// -------- K1: per-(b,i) GEMM + score + global max (pass 1) --------
__global__ void __launch_bounds__(256) k_edge(const float* __restrict__ e,
                                              const float* __restrict__ we) {
    __shared__ float W_s[4096];
    __shared__ float e_s[64*65];
    __shared__ float qrow[64];
    int tid = threadIdx.x, bi = blockIdx.x, b = bi >> 8, i = bi & 255;
    if (tid < 64) qrow[tid] = g_Q[bi*64 + tid];
    __syncthreads();
    for (int idx = tid; idx < 4096; idx += 256) W_s[idx] = we[idx] * qrow[idx & 63];

    int tj = tid & 31, th = tid >> 5;
    const float* Ktb = g_Kt + (b*64 + th*8)*256;
    float* Sout = g_S + ((size_t)((b*8 + th)*256 + i))*256;
    const float4* eg = ((const float4*)e) + (size_t)bi*4096;
    float mymax = -3.402823466e38f;

    for (int ch = 0; ch < 4; ch++) {
        __syncthreads();
        for (int v = tid; v < 1024; v += 256) {
            float4 x = eg[ch*1024 + v];
            float* d = &e_s[(v >> 4)*65 + (v & 15)*4];
            d[0] = x.x; d[1] = x.y; d[2] = x.z; d[3] = x.w;
        }
        __syncthreads();
        unsigned long long acc[8];
#pragma unroll
        for (int a = 0; a < 8; a++) acc[a] = 0ULL;
#pragma unroll 4
        for (int c = 0; c < 64; c++) {
            const float* wrow = W_s + c*64 + th*8;
            unsigned long long w0 = *(const unsigned long long*)(wrow);
            unsigned long long w1 = *(const unsigned long long*)(wrow + 2);
            unsigned long long w2 = *(const unsigned long long*)(wrow + 4);
            unsigned long long w3 = *(const unsigned long long*)(wrow + 6);
            float e0 = e_s[tj*65 + c];
            float e1 = e_s[(tj + 32)*65 + c];
            unsigned long long d0, d1;
            asm("mov.b64 %0,{%1,%1};" : "=l"(d0) : "r"(__float_as_uint(e0)));
            asm("mov.b64 %0,{%1,%1};" : "=l"(d1) : "r"(__float_as_uint(e1)));
            asm("fma.rn.f32x2 %0,%1,%2,%0;" : "+l"(acc[0]) : "l"(d0), "l"(w0));
            asm("fma.rn.f32x2 %0,%1,%2,%0;" : "+l"(acc[1]) : "l"(d0), "l"(w1));
            asm("fma.rn.f32x2 %0,%1,%2,%0;" : "+l"(acc[2]) : "l"(d0), "l"(w2));
            asm("fma.rn.f32x2 %0,%1,%2,%0;" : "+l"(acc[3]) : "l"(d0), "l"(w3));
            asm("fma.rn.f32x2 %0,%1,%2,%0;" : "+l"(acc[4]) : "l"(d1), "l"(w0));
            asm("fma.rn.f32x2 %0,%1,%2,%0;" : "+l"(acc[5]) : "l"(d1), "l"(w1));
            asm("fma.rn.f32x2 %0,%1,%2,%0;" : "+l"(acc[6]) : "l"(d1), "l"(w2));
            asm("fma.rn.f32x2 %0,%1,%2,%0;" : "+l"(acc[7]) : "l"(d1), "l"(w3));
        }
#pragma unroll
        for (int jj = 0; jj < 2; jj++) {
            int j = ch*64 + tj + jj*32;
            float s = 0.f;
#pragma unroll
            for (int pp = 0; pp < 4; pp++) {
                unsigned long long a = acc[jj*4 + pp];
                float lo = __uint_as_float((unsigned int)a);
                float hi = __uint_as_float((unsigned int)(a >> 32));
                s = fmaf(lo, Ktb[(2*pp)*256 + j], s);
                s = fmaf(hi, Ktb[(2*pp + 1)*256 + j], s);
            }
            Sout[j] = s;
            mymax = fmaxf(mymax, s);
        }
    }
#pragma unroll
    for (int off = 16; off; off >>= 1)
        mymax = fmaxf(mymax, __shfl_xor_sync(0xffffffffu, mymax, off));
    if (tj == 0) {
        unsigned int u = __float_as_uint(mymax);
        u = (u & 0x80000000u) ? ~u : (u | 0x80000000u);
        atomicMax(&g_M[b*8 + th], u);
    }
}

// -------- K2: exp/mask/k_RW, denom, PV -> p_attn (pass 2) --------
__global__ void k_soft(const float* __restrict__ mask, const float* __restrict__ kRW) {
    int i = blockIdx.x & 255, bh = blockIdx.x >> 8;
    int b = bh >> 3, h = bh & 7;
    int t = threadIdx.x, j = t;
    unsigned int mu = g_M[bh];
    float m = (mu & 0x80000000u) ? __uint_as_float(mu ^ 0x80000000u) : __uint_as_float(~mu);
    float s = g_S[((size_t)(bh*256 + i))*256 + j];
    float v = __expf(s - m);
    v *= mask[b*256 + i] * mask[b*256 + j] * kRW[((size_t)b*256 + i)*256 + j];
    const float4* V4 = (const float4*)(g_Vt + (((size_t)(b*8 + h)*256) + j)*8);
    float4 va = V4[0], vb = V4[1];
    float vals[9] = {v, v*va.x, v*va.y, v*va.z, v*va.w, v*vb.x, v*vb.y, v*vb.z, v*vb.w};
#pragma unroll
    for (int k = 0; k < 9; k++)
#pragma unroll
        for (int off = 16; off; off >>= 1)
            vals[k] += __shfl_xor_sync(0xffffffffu, vals[k], off);
    __shared__ float sred[8][9];
    __shared__ float fin[9];
    int lane = t & 31, w = t >> 5;
    if (lane == 0)
#pragma unroll
        for (int k = 0; k < 9; k++) sred[w][k] = vals[k];
    __syncthreads();
    if (t < 9) {
        float r = 0.f;
#pragma unroll
        for (int ww = 0; ww < 8; ww++) r += sred[ww][t];
        fin[t] = r;
    }
    __syncthreads();
    if (t < 8) {
        float denom = fmaxf(fin[0], 1e-6f);
        g_pattn[((size_t)(b*256 + i))*64 + h*8 + t] = fin[t + 1] / denom;
    }
}

// -------- K3: h_c = h + p + tanh(p_attn @ wo_p) --------
__global__ void k_hc(const float* __restrict__ hh, const float* __restrict__ p,
                     const float* __restrict__ wo) {
    int bi = blockIdx.x, t = threadIdx.x;
    __shared__ float pa[64];
    pa[t] = g_pattn[bi*64 + t];
    __syncthreads();
    float a = 0.f;
#pragma unroll 8
    for (int c = 0; c < 64; c++) a = fmaf(pa[c], wo[c*64 + t], a);
    g_hc[bi*64 + t] = hh[bi*64 + t] + p[bi*64 + t] + tanhf(a);
}

// -------- K4a: Kc/Vc = h_c @ cq_wkv --------
__global__ void k_kv(const float* __restrict__ wkv) {
    int bi = blockIdx.x, t = threadIdx.x;
    __shared__ float hr[64];
    if (t < 64) hr[t] = g_hc[bi*64 + t];
    __syncthreads();
    float a = 0.f;
#pragma unroll 8
    for (int c = 0; c < 64; c++) a = fmaf(hr[c], wkv[c*128 + t], a);
    if (t < 64) g_Kc[bi*64 + t] = a; else g_Vc[bi*64 + (t - 64)] = a;
}

// -------- K4b: perceiver cross-attention (latents <- nodes) --------
__global__ void k_cross(const float* __restrict__ queries, const float* __restrict__ mask,
                        const float* __restrict__ wq, const float* __restrict__ wo,
                        const float* __restrict__ bo) {
    int blk = blockIdx.x, b = blk >> 5, t = threadIdx.x;
    __shared__ __align__(16) float q2[64];
    __shared__ float sq[64];
    __shared__ float att[64];
    __shared__ float simb[8*256];
    if (t < 64) sq[t] = queries[blk*64 + t];
    __syncthreads();
    if (t < 64) {
        float a = 0.f;
#pragma unroll 8
        for (int c = 0; c < 64; c++) a = fmaf(sq[c], wq[c*64 + t], a);
        q2[t] = a;
    }
    __syncthreads();
    {
        int j = t;
        bool mk = mask[b*256 + j] > 0.5f;
        const float* Kr = g_Kc + ((size_t)(b*256 + j))*64;
#pragma unroll
        for (int h = 0; h < 8; h++) {
            float4 ka = *(const float4*)(Kr + h*8);
            float4 kb = *(const float4*)(Kr + h*8 + 4);
            float4 qa = *(const float4*)(q2 + h*8);
            float4 qb = *(const float4*)(q2 + h*8 + 4);
            float s = ka.x*qa.x + ka.y*qa.y + ka.z*qa.z + ka.w*qa.w
                    + kb.x*qb.x + kb.y*qb.y + kb.z*qb.z + kb.w*qb.w;
            s *= SC;
            if (!mk) s = -3.402823466e38f;
            simb[h*256 + j] = fminf(5.f, fmaxf(-5.f, s));
        }
    }
    __syncthreads();
    int w = t >> 5, lane = t & 31;
    {
        int h = w;
        float m = -3.4e38f;
        for (int j = lane; j < 256; j += 32) m = fmaxf(m, simb[h*256 + j]);
#pragma unroll
        for (int off = 16; off; off >>= 1)
            m = fmaxf(m, __shfl_xor_sync(0xffffffffu, m, off));
        float sum = 0.f, o[8];
#pragma unroll
        for (int d = 0; d < 8; d++) o[d] = 0.f;
        for (int j = lane; j < 256; j += 32) {
            float ev = __expf(simb[h*256 + j] - m);
            sum += ev;
            const float4* V4 = (const float4*)(g_Vc + ((size_t)(b*256 + j))*64 + h*8);
            float4 va = V4[0], vb = V4[1];
            o[0] = fmaf(ev, va.x, o[0]); o[1] = fmaf(ev, va.y, o[1]);
            o[2] = fmaf(ev, va.z, o[2]); o[3] = fmaf(ev, va.w, o[3]);
            o[4] = fmaf(ev, vb.x, o[4]); o[5] = fmaf(ev, vb.y, o[5]);
            o[6] = fmaf(ev, vb.z, o[6]); o[7] = fmaf(ev, vb.w, o[7]);
        }
#pragma unroll
        for (int off = 16; off; off >>= 1) {
            sum += __shfl_xor_sync(0xffffffffu, sum, off);
#pragma unroll
            for (int d = 0; d < 8; d++) o[d] += __shfl_xor_sync(0xffffffffu, o[d], off);
        }
        if (lane == 0) {
            float inv = 1.f / sum;
#pragma unroll
            for (int d = 0; d < 8; d++) att[h*8 + d] = o[d]*inv;
        }
    }
    __syncthreads();
    if (t < 64) {
        float a = bo[t];
#pragma unroll 8
        for (int c = 0; c < 64; c++) a = fmaf(att[c], wo[c*64 + t], a);
        g_q[blk*64 + t] = sq[t] + a;
    }
}

// -------- K5a: latent self-attn projections --------
__global__ void k_selfqkv(const float* __restrict__ wq, const float* __restrict__ wkv) {
    int blk = blockIdx.x, t = threadIdx.x;
    __shared__ float qr[64];
    if (t < 64) qr[t] = g_q[blk*64 + t];
    __syncthreads();
    if (t < 64) {
        float a = 0.f;
#pragma unroll 8
        for (int c = 0; c < 64; c++) a = fmaf(qr[c], wq[c*64 + t], a);
        g_q2[blk*64 + t] = a;
    } else {
        int o = t - 64;
        float a = 0.f;
#pragma unroll 8
        for (int c = 0; c < 64; c++) a = fmaf(qr[c], wkv[c*128 + o], a);
        if (o < 64) g_Kl[blk*64 + o] = a; else g_Vl[blk*64 + (o - 64)] = a;
    }
}

// -------- K5b: latent self-attn core + proj + residual --------
__global__ void k_self(const float* __restrict__ wo, const float* __restrict__ bo) {
    int blk = blockIdx.x, b = blk >> 5, t = threadIdx.x;
    __shared__ float Ks[NLAT*64], Vs[NLAT*64], q2r[64], att[64];
    for (int idx = t; idx < NLAT*64; idx += 256) {
        Ks[idx] = g_Kl[b*NLAT*64 + idx];
        Vs[idx] = g_Vl[b*NLAT*64 + idx];
    }
    if (t < 64) q2r[t] = g_q2[blk*64 + t];
    __syncthreads();
    int h = t >> 5, j = t & 31;
    float s = 0.f;
#pragma unroll
    for (int k = 0; k < 8; k++) s = fmaf(q2r[h*8 + k], Ks[j*64 + h*8 + k], s);
    s *= SC;
    s = fminf(5.f, fmaxf(-5.f, s));
    float m = s;
#pragma unroll
    for (int off = 16; off; off >>= 1)
        m = fmaxf(m, __shfl_xor_sync(0xffffffffu, m, off));
    float ev = __expf(s - m);
    float sum = ev;
#pragma unroll
    for (int off = 16; off; off >>= 1)
        sum += __shfl_xor_sync(0xffffffffu, sum, off);
    float o[8];
#pragma unroll
    for (int d = 0; d < 8; d++) o[d] = ev * Vs[j*64 + h*8 + d];
#pragma unroll
    for (int off = 16; off; off >>= 1)
#pragma unroll
        for (int d = 0; d < 8; d++) o[d] += __shfl_xor_sync(0xffffffffu, o[d], off);
    if (j == 0) {
        float inv = 1.f / sum;
#pragma unroll
        for (int d = 0; d < 8; d++) att[h*8 + d] = o[d]*inv;
    }
    __syncthreads();
    if (t < 64) {
        float a = bo[t];
#pragma unroll 8
        for (int c = 0; c < 64; c++) a = fmaf(att[c], wo[c*64 + t], a);
        g_q[blk*64 + t] += a;
    }
}

// -------- K6: oq_w @ + LN1 + FFN + LN2 -> out --------
__global__ void k_final(const float* __restrict__ oq, const float* __restrict__ g1,
                        const float* __restrict__ b1, const float* __restrict__ w1,
                        const float* __restrict__ w2, const float* __restrict__ g2,
                        const float* __restrict__ b2, float* __restrict__ out) {
    int blk = blockIdx.x, t = threadIdx.x;
    __shared__ float qr[64], x[64], y[64], f1[128], z[64], mv[2];
    if (t < 64) qr[t] = g_q[blk*64 + t];
    __syncthreads();
    if (t < 64) {
        float a = 0.f;
#pragma unroll 8
        for (int c = 0; c < 64; c++) a = fmaf(qr[c], oq[c*64 + t], a);
        x[t] = a;
    }
    __syncthreads();
    if (t < 32) {
        float a = x[t], bb = x[t + 32];
        float su = a + bb, sq = a*a + bb*bb;
#pragma unroll
        for (int off = 16; off; off >>= 1) {
            su += __shfl_xor_sync(0xffffffffu, su, off);
            sq += __shfl_xor_sync(0xffffffffu, sq, off);
        }
        if (t == 0) { mv[0] = su/64.f; mv[1] = sq/64.f - (su/64.f)*(su/64.f); }
    }
    __syncthreads();
    if (t < 64)
        y[t] = (x[t] - mv[0])*rsqrtf(mv[1] + 1e-5f)*g1[t] + b1[t];
    __syncthreads();
    {
        float a = 0.f;
#pragma unroll 8
        for (int c = 0; c < 64; c++) a = fmaf(y[c], w1[c*128 + t], a);
        f1[t] = fmaxf(a, 0.f);
    }
    __syncthreads();
    if (t < 64) {
        float a = 0.f;
#pragma unroll 8
        for (int c = 0; c < 128; c++) a = fmaf(f1[c], w2[c*64 + t], a);
        z[t] = y[t] + a;
    }
    __syncthreads();
    if (t < 32) {
        float a = z[t], bb = z[t + 32];
        float su = a + bb, sq = a*a + bb*bb;
#pragma unroll
        for (int off = 16; off; off >>= 1) {
            su += __shfl_xor_sync(0xffffffffu, su, off);
            sq += __shfl_xor_sync(0xffffffffu, sq, off);
        }
        if (t == 0) { mv[0] = su/64.f; mv[1] = sq/64.f - (su/64.f)*(su/64.f); }
    }
    __syncthreads();
    if (t < 64)
        out[blk*64 + t] = (z[t] - mv[0])*rsqrtf(mv[1] + 1e-5f)*g2[t] + b2[t];
}

extern "C" void kernel_launch(void* const* d_in, const int* in_sizes, int n_in,
                              void* d_out, int out_size) {
    const float* h_    = (const float*)d_in[0];
    const float* p     = (const float*)d_in[1];
    const float* e     = (const float*)d_in[2];
    const float* kRW   = (const float*)d_in[3];
    const float* qrs   = (const float*)d_in[4];
    const float* mask  = (const float*)d_in[5];
    const float* wq_p  = (const float*)d_in[6];
    const float* wk_p  = (const float*)d_in[7];
    const float* we_p  = (const float*)d_in[8];
    const float* wv_p  = (const float*)d_in[9];
    const float* wo_p  = (const float*)d_in[10];
    const float* cq_wq = (const float*)d_in[11];
    const float* cq_wkv= (const float*)d_in[12];
    const float* cq_wo = (const float*)d_in[13];
    const float* cq_bo = (const float*)d_in[14];
    const float* sa_wq = (const float*)d_in[15];
    const float* sa_wkv= (const float*)d_in[16];
    const float* sa_wo = (const float*)d_in[17];
    const float* sa_bo = (const float*)d_in[18];
    const float* oq_w  = (const float*)d_in[19];
    const float* ln1g  = (const float*)d_in[20];
    const float* ln1b  = (const float*)d_in[21];
    const float* fw1   = (const float*)d_in[22];
    const float* fw2   = (const float*)d_in[23];
    const float* ln2g  = (const float*)d_in[24];
    const float* ln2b  = (const float*)d_in[25];
    float* out = (float*)d_out;

    k_qkv   <<<NB*NN, 64>>>(p, wq_p, wk_p, wv_p);
    k_edge  <<<NB*NN, 256>>>(e, we_p);
    k_soft  <<<NB*NH*NN, 256>>>(mask, kRW);
    k_hc    <<<NB*NN, 64>>>(h_, p, wo_p);
    k_kv    <<<NB*NN, 128>>>(cq_wkv);
    k_cross <<<NB*NLAT, 256>>>(qrs, mask, cq_wq, cq_wo, cq_bo);
    for (int l = 0; l < 2; l++) {
        k_selfqkv<<<NB*NLAT, 192>>>(sa_wq + l*4096, sa_wkv + l*8192);
        k_self   <<<NB*NLAT, 256>>>(sa_wo + l*4096, sa_bo + l*64);
    }
    k_final <<<NB*NLAT, 128>>>(oq_w, ln1g, ln1b, fw1, fw2, ln2g, ln2b, out);
}